// round 2
// baseline (speedup 1.0000x reference)
#include <cuda_runtime.h>
#include <cstdint>
#include <cstddef>

// ---------------------------------------------------------------------------
// SpatialAttentionLayer: T=8192 tokens, N=24 joints, D=256, H=8 heads, F=32.
//   q = x_n @ Wq[h,n] + bq ; k/v = x_n @ Wk/Wv[h] + b  (per token, per joint)
//   attn over joints per (t,h); concat heads; residual + LayerNorm(6144)
// Strategy: tf32 mma.sync GEMM for all projections (K1), fused
// attention+residual+LN per token (K2). Weights repacked per joint (prep).
// ---------------------------------------------------------------------------

#define T_TOK 8192
#define NJ    24
#define DIM   256
#define NH    8
#define FD    32
#define JD    6144      // NJ*DIM
#define OUTJ  768       // 3*DIM  (Q|K|V columns)

#define BM 128
#define BN 128
#define BK 32
#define APAD 36
#define BPAD 132

#define SMEM1 ((256*BPAD + 2*BM*APAD + BN) * 4)                    // 172544 B
#define SMEM2 ((192*36 + 6144 + 6144 + 24*260 + 16) * 4)           // 101824 B

// Scratch (static __device__ allocation is the sanctioned path)
__device__ float g_Q[(size_t)T_TOK * NH * NJ * FD];   // [t][h][n][f]
__device__ float g_K[(size_t)T_TOK * NH * NJ * FD];
__device__ float g_V[(size_t)T_TOK * NH * NJ * FD];
__device__ float g_Wt[(size_t)NJ * DIM * OUTJ];        // [n][d][j], tf32-rounded
__device__ float g_bias[NJ * OUTJ];                    // [n][j]

__device__ __forceinline__ unsigned f2tf32(float x) {
    unsigned u;
    asm("cvt.rna.tf32.f32 %0, %1;" : "=r"(u) : "f"(x));
    return u;
}

__device__ __forceinline__ void mma_tf32(float* d, const unsigned* a, const unsigned* b) {
    asm volatile(
        "mma.sync.aligned.m16n8k8.row.col.f32.tf32.tf32.f32 "
        "{%0,%1,%2,%3}, {%4,%5,%6,%7}, {%8,%9}, {%0,%1,%2,%3};\n"
        : "+f"(d[0]), "+f"(d[1]), "+f"(d[2]), "+f"(d[3])
        : "r"(a[0]), "r"(a[1]), "r"(a[2]), "r"(a[3]), "r"(b[0]), "r"(b[1]));
}

// ---------------- prep: repack weights (tf32-rounded) + bias ----------------
__global__ void prep_w_kernel(const float* __restrict__ Wq,
                              const float* __restrict__ Wk,
                              const float* __restrict__ Wv) {
    const size_t total = (size_t)NJ * DIM * OUTJ;
    for (size_t i = (size_t)blockIdx.x * blockDim.x + threadIdx.x; i < total;
         i += (size_t)gridDim.x * blockDim.x) {
        int j = (int)(i % OUTJ);
        size_t nd = i / OUTJ;
        int d = (int)(nd % DIM);
        int n = (int)(nd / DIM);
        int h = (j >> 5) & 7;
        int f = j & 31;
        float v;
        if (j < 256)      v = Wq[(((size_t)h * NJ + n) * DIM + d) * FD + f];
        else if (j < 512) v = Wk[((size_t)h * DIM + d) * FD + f];
        else              v = Wv[((size_t)h * DIM + d) * FD + f];
        g_Wt[i] = __uint_as_float(f2tf32(v));
    }
}

__global__ void prep_b_kernel(const float* __restrict__ bq,
                              const float* __restrict__ bk,
                              const float* __restrict__ bv) {
    int i = blockIdx.x * blockDim.x + threadIdx.x;
    if (i < NJ * OUTJ) {
        int n = i / OUTJ, j = i % OUTJ;
        int h = (j >> 5) & 7;
        int f = j & 31;
        float v;
        if (j < 256)      v = bq[(h * NJ + n) * FD + f];
        else if (j < 512) v = bk[h * FD + f];
        else              v = bv[h * FD + f];
        g_bias[i] = v;
    }
}

// ---------------- K1: QKV projection GEMM (tf32 mma.sync) -------------------
// grid = 144 CTAs: (joint 0..23) x (col-block 0..5 of 128).
// B panel (256x128) resident in SMEM; stream 64 M-tiles of 128 tokens.
__global__ void __launch_bounds__(256, 1)
qkv_gemm_kernel(const float* __restrict__ x) {
    extern __shared__ float sm1[];
    float* Bs     = sm1;                    // [256][BPAD]
    float* As     = sm1 + 256 * BPAD;       // [2][BM][APAD]
    float* bias_s = As + 2 * BM * APAD;     // [BN]

    const int bx = blockIdx.x;
    const int njoint = bx / 6;
    const int nblk   = bx % 6;
    const int tid  = threadIdx.x;
    const int warp = tid >> 5, lane = tid & 31;
    const int g = lane >> 2, tg = lane & 3;
    const int wm = warp >> 2;   // 0..1 -> 64 rows
    const int wn = warp & 3;    // 0..3 -> 32 cols

    // Load resident B panel (already tf32-rounded by prep)
    for (int i = tid; i < 256 * 32; i += 256) {   // 8192 float4
        int d = i >> 5, c4 = i & 31;
        float4 v = *(const float4*)&g_Wt[((size_t)njoint * DIM + d) * OUTJ + nblk * BN + c4 * 4];
        *(float4*)&Bs[d * BPAD + c4 * 4] = v;
    }
    if (tid < BN) bias_s[tid] = g_bias[njoint * OUTJ + nblk * BN + tid];

    float acc[4][4][4];
#pragma unroll
    for (int mt = 0; mt < 4; ++mt)
#pragma unroll
        for (int nt = 0; nt < 4; ++nt)
#pragma unroll
            for (int r = 0; r < 4; ++r) acc[mt][nt][r] = 0.f;

    // ---- prologue: load + store chunk 0 (m-tile 0, kb 0) ----
    float4 rA[4];
    {
        const float* base = x + (size_t)njoint * DIM;   // mt=0, kb=0
#pragma unroll
        for (int i = 0; i < 4; ++i) {
            int lin = tid + 256 * i;
            int row = lin >> 3, c4 = lin & 7;
            rA[i] = *(const float4*)&base[(size_t)row * JD + c4 * 4];
        }
#pragma unroll
        for (int i = 0; i < 4; ++i) {
            int lin = tid + 256 * i;
            int row = lin >> 3, c4 = lin & 7;
            float4 v = rA[i];
            v.x = __uint_as_float(f2tf32(v.x));
            v.y = __uint_as_float(f2tf32(v.y));
            v.z = __uint_as_float(f2tf32(v.z));
            v.w = __uint_as_float(f2tf32(v.w));
            *(float4*)&As[row * APAD + c4 * 4] = v;
        }
    }
    __syncthreads();

#pragma unroll 1
    for (int c = 0; c < 512; ++c) {           // chunk = (m-tile c>>3, kb c&7)
        float4 rN[4];
        if (c < 511) {
            int cn = c + 1;
            int mt = cn >> 3, kb = cn & 7;
            const float* base = x + (size_t)mt * BM * JD + njoint * DIM + kb * BK;
#pragma unroll
            for (int i = 0; i < 4; ++i) {
                int lin = tid + 256 * i;
                int row = lin >> 3, c4 = lin & 7;
                rN[i] = *(const float4*)&base[(size_t)row * JD + c4 * 4];
            }
        }

        // ---- compute on stage c&1 ----
        const float* A0 = As + (c & 1) * BM * APAD;
#pragma unroll
        for (int kk = 0; kk < 4; ++kk) {
            unsigned a[4][4], b[4][2];
#pragma unroll
            for (int mt = 0; mt < 4; ++mt) {
                int r0 = wm * 64 + mt * 16;
                a[mt][0] = __float_as_uint(A0[(r0 + g)     * APAD + kk * 8 + tg]);
                a[mt][1] = __float_as_uint(A0[(r0 + 8 + g) * APAD + kk * 8 + tg]);
                a[mt][2] = __float_as_uint(A0[(r0 + g)     * APAD + kk * 8 + tg + 4]);
                a[mt][3] = __float_as_uint(A0[(r0 + 8 + g) * APAD + kk * 8 + tg + 4]);
            }
            int kglob = (c & 7) * BK + kk * 8;
#pragma unroll
            for (int nt = 0; nt < 4; ++nt) {
                int cc = wn * 32 + nt * 8 + g;
                b[nt][0] = __float_as_uint(Bs[(kglob + tg)     * BPAD + cc]);
                b[nt][1] = __float_as_uint(Bs[(kglob + 4 + tg) * BPAD + cc]);
            }
#pragma unroll
            for (int mt = 0; mt < 4; ++mt)
#pragma unroll
                for (int nt = 0; nt < 4; ++nt)
                    mma_tf32(acc[mt][nt], a[mt], b[nt]);
        }

        // ---- epilogue at end of each m-tile ----
        if ((c & 7) == 7) {
            int mtile = c >> 3;
            int base_t = mtile * BM + wm * 64;
#pragma unroll
            for (int mt = 0; mt < 4; ++mt)
#pragma unroll
                for (int nt = 0; nt < 4; ++nt) {
                    int t0 = base_t + mt * 16 + g;
                    int jl = wn * 32 + nt * 8 + tg * 2;
                    int jg = nblk * BN + jl;
                    float* out = (jg < 256) ? g_Q : ((jg < 512) ? g_K : g_V);
                    int j2 = jg & 255;
                    int h = j2 >> 5, f = j2 & 31;
                    float b0 = bias_s[jl], b1 = bias_s[jl + 1];
                    size_t i0 = (((size_t)t0 * NH + h) * NJ + njoint) * FD + f;
                    float2 v0 = make_float2(acc[mt][nt][0] + b0, acc[mt][nt][1] + b1);
                    *(float2*)&out[i0] = v0;
                    size_t i1 = (((size_t)(t0 + 8) * NH + h) * NJ + njoint) * FD + f;
                    float2 v1 = make_float2(acc[mt][nt][2] + b0, acc[mt][nt][3] + b1);
                    *(float2*)&out[i1] = v1;
                    acc[mt][nt][0] = acc[mt][nt][1] = acc[mt][nt][2] = acc[mt][nt][3] = 0.f;
                }
        }

        if (c < 511) {
            // fill the *other* stage (safe: last read of it was before prev sync)
            float* dst = As + ((c + 1) & 1) * BM * APAD;
#pragma unroll
            for (int i = 0; i < 4; ++i) {
                int lin = tid + 256 * i;
                int row = lin >> 3, c4 = lin & 7;
                float4 v = rN[i];
                v.x = __uint_as_float(f2tf32(v.x));
                v.y = __uint_as_float(f2tf32(v.y));
                v.z = __uint_as_float(f2tf32(v.z));
                v.w = __uint_as_float(f2tf32(v.w));
                *(float4*)&dst[row * APAD + c4 * 4] = v;
            }
            __syncthreads();
        }
    }
}

// -------- K2: per-token attention + residual + LayerNorm --------------------
// grid = 8192 CTAs of 256 threads; warp h handles head h, lane n handles row n.
__global__ void __launch_bounds__(256, 2)
attn_ln_kernel(const float* __restrict__ x, const float* __restrict__ gamma,
               const float* __restrict__ beta, float* __restrict__ y) {
    extern __shared__ float sm2[];
    float* qs   = sm2;                 // [192][36] padded (row = h*24+n)
    float* ks   = qs + 192 * 36;       // [6144] flat [h][m][f]
    float* vs   = ks + 6144;           // [6144]
    float* outs = vs + 6144;           // [24][260]
    float* red  = outs + 24 * 260;     // [16]

    const int t = blockIdx.x;
    const int tid = threadIdx.x;
    const int warp = tid >> 5, lane = tid & 31;

    const float* Qg = g_Q + (size_t)t * JD;
    const float* Kg = g_K + (size_t)t * JD;
    const float* Vg = g_V + (size_t)t * JD;

    for (int i = tid; i < 1536; i += 256) {        // q: padded rows of 32
        float4 v = *(const float4*)&Qg[i * 4];
        int r = i >> 3, c4 = i & 7;
        *(float4*)&qs[r * 36 + c4 * 4] = v;
    }
    for (int i = tid; i < 1536; i += 256)
        *(float4*)&ks[i * 4] = *(const float4*)&Kg[i * 4];
    for (int i = tid; i < 1536; i += 256)
        *(float4*)&vs[i * 4] = *(const float4*)&Vg[i * 4];
    __syncthreads();

    if (lane < NJ) {
        const int h = warp, n = lane;
        const float scale = 0.17677669529663687f;  // 1/sqrt(32)
        float q[32];
        int r = h * NJ + n;
#pragma unroll
        for (int f4 = 0; f4 < 8; ++f4) {
            float4 v = *(const float4*)&qs[r * 36 + f4 * 4];
            q[f4 * 4 + 0] = v.x * scale; q[f4 * 4 + 1] = v.y * scale;
            q[f4 * 4 + 2] = v.z * scale; q[f4 * 4 + 3] = v.w * scale;
        }
        float sc[NJ];
        const float* kh = ks + h * (NJ * FD);
#pragma unroll
        for (int m = 0; m < NJ; ++m) {
            float s = 0.f;
            const float4* kr = (const float4*)(kh + m * FD);
#pragma unroll
            for (int f4 = 0; f4 < 8; ++f4) {
                float4 kv = kr[f4];
                s += q[f4 * 4 + 0] * kv.x + q[f4 * 4 + 1] * kv.y
                   + q[f4 * 4 + 2] * kv.z + q[f4 * 4 + 3] * kv.w;
            }
            sc[m] = s;
        }
        float mx = sc[0];
#pragma unroll
        for (int m = 1; m < NJ; ++m) mx = fmaxf(mx, sc[m]);
        float sum = 0.f;
#pragma unroll
        for (int m = 0; m < NJ; ++m) { sc[m] = __expf(sc[m] - mx); sum += sc[m]; }
        float inv = 1.f / sum;

        float o[32];
#pragma unroll
        for (int f = 0; f < 32; ++f) o[f] = 0.f;
        const float* vh = vs + h * (NJ * FD);
#pragma unroll
        for (int m = 0; m < NJ; ++m) {
            float a = sc[m] * inv;
            const float4* vr = (const float4*)(vh + m * FD);
#pragma unroll
            for (int f4 = 0; f4 < 8; ++f4) {
                float4 vv = vr[f4];
                o[f4 * 4 + 0] += a * vv.x; o[f4 * 4 + 1] += a * vv.y;
                o[f4 * 4 + 2] += a * vv.z; o[f4 * 4 + 3] += a * vv.w;
            }
        }
#pragma unroll
        for (int f = 0; f < 32; ++f) outs[n * 260 + h * 32 + f] = o[f];
    }
    __syncthreads();

    // residual + LayerNorm over 6144
    const float* xg = x + (size_t)t * JD;
    float yv[24];
    float s1 = 0.f, s2 = 0.f;
#pragma unroll
    for (int i = 0; i < 24; ++i) {
        int idx = i * 256 + tid;
        float v = xg[idx] + outs[(idx >> 8) * 260 + (idx & 255)];
        yv[i] = v; s1 += v; s2 += v * v;
    }
#pragma unroll
    for (int o = 16; o; o >>= 1) {
        s1 += __shfl_xor_sync(0xffffffffu, s1, o);
        s2 += __shfl_xor_sync(0xffffffffu, s2, o);
    }
    if (lane == 0) { red[warp] = s1; red[warp + 8] = s2; }
    __syncthreads();
    float S1 = 0.f, S2 = 0.f;
#pragma unroll
    for (int w = 0; w < 8; ++w) { S1 += red[w]; S2 += red[w + 8]; }
    const float mu = S1 * (1.0f / JD);
    const float var = S2 * (1.0f / JD) - mu * mu;
    const float rstd = rsqrtf(var + 1e-5f);
    float* yt = y + (size_t)t * JD;
#pragma unroll
    for (int i = 0; i < 24; ++i) {
        int idx = i * 256 + tid;
        yt[idx] = (yv[i] - mu) * rstd * gamma[idx] + beta[idx];
    }
}

// ---------------------------------------------------------------------------
extern "C" void kernel_launch(void* const* d_in, const int* in_sizes, int n_in,
                              void* d_out, int out_size) {
    const float* x     = (const float*)d_in[0];
    const float* Wq    = (const float*)d_in[1];
    const float* bq    = (const float*)d_in[2];
    const float* Wk    = (const float*)d_in[3];
    const float* bk    = (const float*)d_in[4];
    const float* Wv    = (const float*)d_in[5];
    const float* bv    = (const float*)d_in[6];
    const float* gamma = (const float*)d_in[7];
    const float* beta  = (const float*)d_in[8];
    float* y = (float*)d_out;

    cudaFuncSetAttribute(qkv_gemm_kernel, cudaFuncAttributeMaxDynamicSharedMemorySize, SMEM1);
    cudaFuncSetAttribute(attn_ln_kernel,  cudaFuncAttributeMaxDynamicSharedMemorySize, SMEM2);

    prep_w_kernel<<<4608, 256>>>(Wq, Wk, Wv);
    prep_b_kernel<<<72, 256>>>(bq, bk, bv);
    qkv_gemm_kernel<<<NJ * 6, 256, SMEM1>>>(x);
    attn_ln_kernel<<<T_TOK, 256, SMEM2>>>(x, gamma, beta, y);
}

// round 4
// speedup vs baseline: 1.2777x; 1.2777x over previous
#include <cuda_runtime.h>
#include <cstdint>
#include <cstddef>

#define T_TOK 8192
#define NJ    24
#define NH    8
#define FD    32
#define JD    6144
#define OUTJ  768

__device__ float g_Q[(size_t)T_TOK * JD];   // [t][h][n][f]
__device__ float g_K[(size_t)T_TOK * JD];
__device__ float g_V[(size_t)T_TOK * JD];
__device__ float g_Wt[(size_t)NJ * OUTJ * 256];   // [n][j][d], tf32-rounded
__device__ float g_bias[NJ * OUTJ];

__device__ __forceinline__ uint32_t smem_u32(const void* p) {
    uint32_t a;
    asm("{ .reg .u64 t; cvta.to.shared.u64 t, %1; cvt.u32.u64 %0, t; }" : "=r"(a) : "l"(p));
    return a;
}
__device__ __forceinline__ unsigned f2tf32(float x) {
    unsigned u;
    asm("cvt.rna.tf32.f32 %0, %1;" : "=r"(u) : "f"(x));
    return u;
}
__device__ __forceinline__ void mma_tf32(float* d, const unsigned* a, const unsigned* b) {
    asm volatile(
        "mma.sync.aligned.m16n8k8.row.col.f32.tf32.tf32.f32 "
        "{%0,%1,%2,%3}, {%4,%5,%6,%7}, {%8,%9}, {%0,%1,%2,%3};\n"
        : "+f"(d[0]), "+f"(d[1]), "+f"(d[2]), "+f"(d[3])
        : "r"(a[0]), "r"(a[1]), "r"(a[2]), "r"(a[3]), "r"(b[0]), "r"(b[1]));
}
__device__ __forceinline__ void cp16(uint32_t d, const void* s) {
    asm volatile("cp.async.cg.shared.global [%0], [%1], 16;" :: "r"(d), "l"(s));
}
#define CPC()  asm volatile("cp.async.commit_group;" ::: "memory")
#define CPW(n) asm volatile("cp.async.wait_group %0;" :: "n"(n) : "memory")

// ------------------------------- prep ---------------------------------------
__global__ void prep_w_kernel(const float* __restrict__ Wq, const float* __restrict__ Wk,
                              const float* __restrict__ Wv) {
    const size_t total = (size_t)NJ * OUTJ * 256;
    for (size_t i = (size_t)blockIdx.x * blockDim.x + threadIdx.x; i < total;
         i += (size_t)gridDim.x * blockDim.x) {
        int d = (int)(i & 255);
        size_t nj = i >> 8;
        int j = (int)(nj % OUTJ), n = (int)(nj / OUTJ);
        int h = (j >> 5) & 7, f = j & 31;
        float v;
        if (j < 256)      v = Wq[(((size_t)h * NJ + n) * 256 + d) * FD + f];
        else if (j < 512) v = Wk[((size_t)h * 256 + d) * FD + f];
        else              v = Wv[((size_t)h * 256 + d) * FD + f];
        g_Wt[i] = __uint_as_float(f2tf32(v));
    }
}
__global__ void prep_b_kernel(const float* __restrict__ bq, const float* __restrict__ bk,
                              const float* __restrict__ bv) {
    int i = blockIdx.x * blockDim.x + threadIdx.x;
    if (i < NJ * OUTJ) {
        int n = i / OUTJ, j = i % OUTJ, h = (j >> 5) & 7, f = j & 31;
        float v;
        if (j < 256)      v = bq[(h * NJ + n) * FD + f];
        else if (j < 512) v = bk[h * FD + f];
        else              v = bv[h * FD + f];
        g_bias[i] = v;
    }
}

// ------------------ K1: tf32 mma.sync QKV GEMM, cp.async 3-stage -------------
// 144 CTAs = 24 joints x 6 col-blocks(128). Per CTA: C[8192x128]=A[8192x256]B^T
// CTA tile 256x128, 8 warps as 4(m) x 2(n), warp tile 64x64.
// SMEM: B panel [n=128][k=256] f32 swizzled (128KB) resident;
//       A 3 stages x [256 rows][32 k] f32 swizzled (96KB); bias 512B.
#define OFF_B    0
#define OFF_A    131072
#define OFF_BIAS 229376
#define SMEM1    229888

__global__ void __launch_bounds__(256, 1)
qkv_gemm2_kernel(const float* __restrict__ x) {
    extern __shared__ char sm[];
    const uint32_t sb = smem_u32(sm);
    float* bias_s = (float*)(sm + OFF_BIAS);
    const int tid = threadIdx.x, warp = tid >> 5, lane = tid & 31;
    const int g = lane >> 2, tg = lane & 3;
    const int wm = warp >> 1, wn = warp & 1;
    const int nj = blockIdx.x / 6, jb = blockIdx.x % 6;

    // prologue group 0: B panel + A chunk 0
    {
        const float* W = g_Wt + (size_t)(nj * OUTJ + jb * 128) * 256;
#pragma unroll
        for (int it = 0; it < 32; ++it) {
            int i = tid + 256 * it;            // 8192 16B-chunks
            int row = i >> 6, c4 = i & 63;
            cp16(sb + OFF_B + (uint32_t)(row * 1024 + ((c4 ^ (row & 7)) << 4)),
                 W + row * 256 + c4 * 4);
        }
        const float* xb = x + (size_t)nj * 256;            // mt=0, kb=0
#pragma unroll
        for (int it = 0; it < 8; ++it) {
            int i = tid + 256 * it;            // 2048 16B-chunks
            int row = i >> 3, c4 = i & 7;
            cp16(sb + OFF_A + (uint32_t)(row * 128 + ((c4 ^ (row & 7)) << 4)),
                 xb + (size_t)row * JD + c4 * 4);
        }
        if (tid < 128) bias_s[tid] = g_bias[nj * OUTJ + jb * 128 + tid];
        CPC();
        // group 1: A chunk 1 (mt=0, kb=1) -> stage 1
        const float* xb1 = xb + 32;
#pragma unroll
        for (int it = 0; it < 8; ++it) {
            int i = tid + 256 * it;
            int row = i >> 3, c4 = i & 7;
            cp16(sb + OFF_A + 32768u + (uint32_t)(row * 128 + ((c4 ^ (row & 7)) << 4)),
                 xb1 + (size_t)row * JD + c4 * 4);
        }
        CPC();
    }

    float acc[4][8][4];
#pragma unroll
    for (int mt = 0; mt < 4; ++mt)
#pragma unroll
        for (int nt = 0; nt < 8; ++nt)
#pragma unroll
            for (int r = 0; r < 4; ++r) acc[mt][nt][r] = 0.f;

    // per-lane row base byte offsets
    uint32_t aRow[4], bRow[8];
#pragma unroll
    for (int mt = 0; mt < 4; ++mt) aRow[mt] = (uint32_t)((wm * 64 + mt * 16 + g) * 128 + tg * 4);
#pragma unroll
    for (int nt = 0; nt < 8; ++nt) bRow[nt] = (uint32_t)((wn * 64 + nt * 8 + g) * 1024 + tg * 4);

#pragma unroll 1
    for (int c = 0; c < 256; ++c) {           // chunk = (mtile c>>3, kb c&7)
        CPW(1);                                // chunk c's stage ready
        __syncthreads();                       // also: all warps done with stage (c+2)%3
        if (c + 2 < 256) {
            int cn = c + 2;
            const float* xb = x + (size_t)(cn >> 3) * 256 * JD + (size_t)nj * 256 + (cn & 7) * 32;
            uint32_t stb = sb + OFF_A + (uint32_t)(cn % 3) * 32768u;
#pragma unroll
            for (int it = 0; it < 8; ++it) {
                int i = tid + 256 * it;
                int row = i >> 3, c4 = i & 7;
                cp16(stb + (uint32_t)(row * 128 + ((c4 ^ (row & 7)) << 4)),
                     xb + (size_t)row * JD + c4 * 4);
            }
        }
        CPC();

        const char* A0 = sm + OFF_A + (c % 3) * 32768;
        const char* B0 = sm + OFF_B + (c & 7) * 128;     // kb*8 chunk offset
#pragma unroll
        for (int kk = 0; kk < 4; ++kk) {
            const uint32_t x0 = (uint32_t)(((2 * kk) ^ g) << 4);
            const uint32_t x1 = (uint32_t)(((2 * kk + 1) ^ g) << 4);
            unsigned a[4][4], b[8][2];
#pragma unroll
            for (int mt = 0; mt < 4; ++mt) {
                a[mt][0] = *(const unsigned*)(A0 + aRow[mt] + x0);
                a[mt][1] = *(const unsigned*)(A0 + aRow[mt] + 1024 + x0);
                a[mt][2] = *(const unsigned*)(A0 + aRow[mt] + x1);
                a[mt][3] = *(const unsigned*)(A0 + aRow[mt] + 1024 + x1);
            }
#pragma unroll
            for (int nt = 0; nt < 8; ++nt) {
                b[nt][0] = *(const unsigned*)(B0 + bRow[nt] + x0);
                b[nt][1] = *(const unsigned*)(B0 + bRow[nt] + x1);
            }
#pragma unroll
            for (int mt = 0; mt < 4; ++mt)
#pragma unroll
                for (int nt = 0; nt < 8; ++nt)
                    mma_tf32(acc[mt][nt], a[mt], b[nt]);
        }

        if ((c & 7) == 7) {                    // epilogue for this 256-row m-tile
            const int rbase = (c >> 3) * 256 + wm * 64 + g;
#pragma unroll
            for (int mt = 0; mt < 4; ++mt)
#pragma unroll
                for (int nt = 0; nt < 8; ++nt) {
                    int jl = wn * 64 + nt * 8 + tg * 2;
                    int jg = jb * 128 + jl;
                    float* outp = (jg < 256) ? g_Q : ((jg < 512) ? g_K : g_V);
                    int h = (jg >> 5) & 7, f = jg & 31;
                    float b0 = bias_s[jl], b1 = bias_s[jl + 1];
                    size_t o0 = (size_t)(rbase + mt * 16) * JD + h * OUTJ + nj * 32 + f;
                    float2 v0 = make_float2(acc[mt][nt][0] + b0, acc[mt][nt][1] + b1);
                    *(float2*)&outp[o0] = v0;
                    float2 v1 = make_float2(acc[mt][nt][2] + b0, acc[mt][nt][3] + b1);
                    *(float2*)&outp[o0 + 8 * JD] = v1;
                    acc[mt][nt][0] = acc[mt][nt][1] = acc[mt][nt][2] = acc[mt][nt][3] = 0.f;
                }
        }
    }
}

// -------- K2: persistent cp.async-pipelined attention + residual + LN -------
#define GRID2   304
#define STAGE_F 12288
#define SMEM2   ((2 * STAGE_F + 16) * 4)

__global__ void __launch_bounds__(256)
attn_ln2_kernel(const float* __restrict__ x, const float* __restrict__ gamma,
                const float* __restrict__ beta, float* __restrict__ y) {
    extern __shared__ float sm2[];
    float* red = sm2 + 2 * STAGE_F;
    const uint32_t sb = smem_u32(sm2);
    const int tid = threadIdx.x, warp = tid >> 5, lane = tid & 31;
    const int t0 = blockIdx.x;

    {   // prologue: stage 0 <- token t0
        const float* Kg = g_K + (size_t)t0 * JD;
        const float* Vg = g_V + (size_t)t0 * JD;
#pragma unroll
        for (int it = 0; it < 6; ++it) {
            int i = tid + 256 * it;
            cp16(sb + (uint32_t)i * 16, Kg + i * 4);
            cp16(sb + 24576u + (uint32_t)i * 16, Vg + i * 4);
        }
        CPC();
    }
    int it_i = 0;
#pragma unroll 1
    for (int t = t0; t < T_TOK; t += GRID2, ++it_i) {
        const int s = it_i & 1;
        CPW(0);                 // this iteration's k/v staged
        __syncthreads();        // all warps past previous compute; stage s^1 free
        const int tn = t + GRID2;
        if (tn < T_TOK) {       // prefetch next token into the other stage
            const float* Kg = g_K + (size_t)tn * JD;
            const float* Vg = g_V + (size_t)tn * JD;
            uint32_t db = sb + (uint32_t)(s ^ 1) * (STAGE_F * 4);
#pragma unroll
            for (int it = 0; it < 6; ++it) {
                int i = tid + 256 * it;
                cp16(db + (uint32_t)i * 16, Kg + i * 4);
                cp16(db + 24576u + (uint32_t)i * 16, Vg + i * 4);
            }
        }
        CPC();

        const float* ks = sm2 + s * STAGE_F;
        const float* vs = ks + 6144;
        const int h = warp, n = lane;
        float s1 = 0.f, s2 = 0.f, yv[32];

        if (n < NJ) {
            const float SC = 0.17677669529663687f;  // 1/sqrt(32)
            float q[32];
            const float* qg = g_Q + (size_t)t * JD + h * OUTJ + n * 32;
#pragma unroll
            for (int f4 = 0; f4 < 8; ++f4) {
                float4 v = *(const float4*)&qg[f4 * 4];
                q[4*f4+0] = v.x * SC; q[4*f4+1] = v.y * SC;
                q[4*f4+2] = v.z * SC; q[4*f4+3] = v.w * SC;
            }
            float sc[NJ];
            const float* kh = ks + h * OUTJ;
#pragma unroll
            for (int m = 0; m < NJ; ++m) {
                const float4* kr = (const float4*)(kh + m * 32);
                float sv = 0.f;
#pragma unroll
                for (int f4 = 0; f4 < 8; ++f4) {
                    float4 kv = kr[f4];
                    sv += q[4*f4+0]*kv.x + q[4*f4+1]*kv.y + q[4*f4+2]*kv.z + q[4*f4+3]*kv.w;
                }
                sc[m] = sv;
            }
            float mx = sc[0];
#pragma unroll
            for (int m = 1; m < NJ; ++m) mx = fmaxf(mx, sc[m]);
            float sum = 0.f;
#pragma unroll
            for (int m = 0; m < NJ; ++m) { sc[m] = __expf(sc[m] - mx); sum += sc[m]; }
            const float inv = 1.f / sum;

            const float* xg = x + (size_t)t * JD + n * 256 + h * 32;
#pragma unroll
            for (int f4 = 0; f4 < 8; ++f4) {
                float4 v = *(const float4*)&xg[f4 * 4];
                yv[4*f4+0] = v.x; yv[4*f4+1] = v.y; yv[4*f4+2] = v.z; yv[4*f4+3] = v.w;
            }
            const float* vh = vs + h * OUTJ;
#pragma unroll
            for (int m = 0; m < NJ; ++m) {
                float a = sc[m] * inv;
                const float4* vr = (const float4*)(vh + m * 32);
#pragma unroll
                for (int f4 = 0; f4 < 8; ++f4) {
                    float4 vv = vr[f4];
                    yv[4*f4+0] += a*vv.x; yv[4*f4+1] += a*vv.y;
                    yv[4*f4+2] += a*vv.z; yv[4*f4+3] += a*vv.w;
                }
            }
#pragma unroll
            for (int f = 0; f < 32; ++f) { s1 += yv[f]; s2 += yv[f] * yv[f]; }
        }
#pragma unroll
        for (int o = 16; o; o >>= 1) {
            s1 += __shfl_xor_sync(0xffffffffu, s1, o);
            s2 += __shfl_xor_sync(0xffffffffu, s2, o);
        }
        if (lane == 0) { red[warp] = s1; red[warp + 8] = s2; }
        __syncthreads();
        float S1 = 0.f, S2 = 0.f;
#pragma unroll
        for (int w = 0; w < 8; ++w) { S1 += red[w]; S2 += red[w + 8]; }
        const float mu = S1 * (1.0f / JD);
        const float var = S2 * (1.0f / JD) - mu * mu;
        const float rstd = rsqrtf(var + 1e-5f);
        if (n < NJ) {
            const int base = n * 256 + h * 32;
            const float* gg = gamma + base;
            const float* bb = beta + base;
            float* yt = y + (size_t)t * JD + base;
#pragma unroll
            for (int f4 = 0; f4 < 8; ++f4) {
                float4 gv = *(const float4*)&gg[f4 * 4];
                float4 bv = *(const float4*)&bb[f4 * 4];
                float4 o;
                o.x = (yv[4*f4+0] - mu) * rstd * gv.x + bv.x;
                o.y = (yv[4*f4+1] - mu) * rstd * gv.y + bv.y;
                o.z = (yv[4*f4+2] - mu) * rstd * gv.z + bv.z;
                o.w = (yv[4*f4+3] - mu) * rstd * gv.w + bv.w;
                *(float4*)&yt[f4 * 4] = o;
            }
        }
    }
}

// ---------------------------------------------------------------------------
extern "C" void kernel_launch(void* const* d_in, const int* in_sizes, int n_in,
                              void* d_out, int out_size) {
    const float* x     = (const float*)d_in[0];
    const float* Wq    = (const float*)d_in[1];
    const float* bq    = (const float*)d_in[2];
    const float* Wk    = (const float*)d_in[3];
    const float* bk    = (const float*)d_in[4];
    const float* Wv    = (const float*)d_in[5];
    const float* bv    = (const float*)d_in[6];
    const float* gamma = (const float*)d_in[7];
    const float* beta  = (const float*)d_in[8];
    float* y = (float*)d_out;

    cudaFuncSetAttribute(qkv_gemm2_kernel, cudaFuncAttributeMaxDynamicSharedMemorySize, SMEM1);
    cudaFuncSetAttribute(attn_ln2_kernel,  cudaFuncAttributeMaxDynamicSharedMemorySize, SMEM2);

    prep_w_kernel<<<4608, 256>>>(Wq, Wk, Wv);
    prep_b_kernel<<<72, 256>>>(bq, bk, bv);
    qkv_gemm2_kernel<<<NJ * 6, 256, SMEM1>>>(x);
    attn_ln2_kernel<<<GRID2, 256, SMEM2>>>(x, gamma, beta, y);
}